// round 2
// baseline (speedup 1.0000x reference)
#include <cuda_runtime.h>
#include <math.h>

#define L      2304
#define DM     128
#define DI     256
#define DS     16
#define DTR    8
#define NPROJ  40   // DTR + 2*DS
#define NDEPTH 8
#define CH     16
#define NC     (L/CH)   // 144

// ---------------- scratch (device globals; no allocations) ----------------
__device__ float g_seq[L*DM];
__device__ float g_tmp[L*DM];
__device__ float g_xz [L*2*DI];
__device__ float g_xc [L*DI];
__device__ float g_dbl[L*NPROJ];
__device__ float g_dt [L*DI];
__device__ float g_y  [L*DI];
__device__ float g_chA[NC*DI*DS];
__device__ float g_chB[NC*DI*DS];
__device__ float g_h0 [NC*DI*DS];

// ---------------- transpose in: x[c, l] -> seq[l, c] ----------------
__global__ void transpose_in_k(const float* __restrict__ x) {
    __shared__ float t[32][33];
    int l0 = blockIdx.x * 32, c0 = blockIdx.y * 32;
    int tx = threadIdx.x, ty = threadIdx.y;
    #pragma unroll
    for (int i = ty; i < 32; i += 8)
        t[i][tx] = x[(c0 + i) * L + l0 + tx];
    __syncthreads();
    #pragma unroll
    for (int i = ty; i < 32; i += 8)
        g_seq[(l0 + i) * DM + c0 + tx] = t[tx][i];
}

// ---------------- transpose out: seq[l, c] -> out[c, l] ----------------
__global__ void transpose_out_k(float* __restrict__ out) {
    __shared__ float t[32][33];
    int l0 = blockIdx.x * 32, c0 = blockIdx.y * 32;
    int tx = threadIdx.x, ty = threadIdx.y;
    #pragma unroll
    for (int i = ty; i < 32; i += 8)
        t[i][tx] = g_seq[(l0 + i) * DM + c0 + tx];
    __syncthreads();
    #pragma unroll
    for (int i = ty; i < 32; i += 8)
        out[(c0 + i) * L + l0 + tx] = t[tx][i];
}

// ---------------- generic fp32 GEMM: C[M,N] = A[M,K] @ B[K,N] ----------------
// BM=BN=64, BK=16, 256 threads, 4x4 register tile per thread.
__global__ void gemm_k(const float* __restrict__ A, const float* __restrict__ B,
                       float* __restrict__ C, int M, int N, int K) {
    __shared__ float As[16][68];
    __shared__ float Bs[16][64];
    int tid = threadIdx.x;
    int tr = tid >> 4, tc = tid & 15;
    int row0 = blockIdx.y * 64, col0 = blockIdx.x * 64;
    float acc[4][4] = {};
    for (int k0 = 0; k0 < K; k0 += 16) {
        #pragma unroll
        for (int i = 0; i < 4; i++) {
            int li = i * 256 + tid;
            int k = li & 15, m = li >> 4;
            As[k][m] = A[(row0 + m) * K + k0 + k];
        }
        #pragma unroll
        for (int i = 0; i < 4; i++) {
            int li = i * 256 + tid;
            int n = li & 63, k = li >> 6;
            int col = col0 + n;
            Bs[k][n] = (col < N) ? B[(k0 + k) * N + col] : 0.f;
        }
        __syncthreads();
        #pragma unroll
        for (int k = 0; k < 16; k++) {
            float a[4], b[4];
            #pragma unroll
            for (int i = 0; i < 4; i++) a[i] = As[k][tr * 4 + i];
            #pragma unroll
            for (int j = 0; j < 4; j++) b[j] = Bs[k][tc * 4 + j];
            #pragma unroll
            for (int i = 0; i < 4; i++)
                #pragma unroll
                for (int j = 0; j < 4; j++)
                    acc[i][j] += a[i] * b[j];
        }
        __syncthreads();
    }
    #pragma unroll
    for (int i = 0; i < 4; i++) {
        int r = row0 + tr * 4 + i;
        #pragma unroll
        for (int j = 0; j < 4; j++) {
            int c = col0 + tc * 4 + j;
            if (c < N) C[r * N + c] = acc[i][j];
        }
    }
}

// ---------------- causal depthwise conv (width 4) + SiLU ----------------
__global__ void conv_silu_k(const float* __restrict__ cw, const float* __restrict__ cb) {
    int l = blockIdx.x, d = threadIdx.x;
    float acc = cb[d];
    #pragma unroll
    for (int k = 0; k < 4; k++) {
        int ll = l + k - 3;
        if (ll >= 0) acc += g_xz[ll * (2 * DI) + d] * cw[d * 4 + k];
    }
    acc = acc / (1.f + __expf(-acc));
    g_xc[l * DI + d] = acc;
}

// ---------------- dt = softplus(dt_r @ W_dt + b_dt) ----------------
__global__ void dt_k(const float* __restrict__ Wdt, const float* __restrict__ bdt) {
    int l = blockIdx.x, d = threadIdx.x;
    __shared__ float r[DTR];
    if (d < DTR) r[d] = g_dbl[l * NPROJ + d];
    __syncthreads();
    float acc = bdt[d];
    #pragma unroll
    for (int k = 0; k < DTR; k++) acc += r[k] * Wdt[k * DI + d];
    float sp = (acc > 20.f) ? acc : log1pf(__expf(acc));
    g_dt[l * DI + d] = sp;
}

// ---------------- scan pass 1: per-chunk (prod dA, local b) ----------------
__global__ void scan1_k(const float* __restrict__ Alog) {
    int blk = blockIdx.x, d = threadIdx.x;
    __shared__ float Bs_s[CH][DS];
    {
        int step = threadIdx.x >> 4, s = threadIdx.x & 15;
        Bs_s[step][s] = g_dbl[(blk * CH + step) * NPROJ + DTR + s];
    }
    __syncthreads();
    float Arow[DS], a[DS], b[DS];
    #pragma unroll
    for (int s = 0; s < DS; s++) {
        Arow[s] = -__expf(Alog[d * DS + s]);
        a[s] = 1.f; b[s] = 0.f;
    }
    #pragma unroll 4
    for (int step = 0; step < CH; step++) {
        int l = blk * CH + step;
        float dt = g_dt[l * DI + d], xc = g_xc[l * DI + d];
        float dtxc = dt * xc;
        #pragma unroll
        for (int s = 0; s < DS; s++) {
            float dA = __expf(dt * Arow[s]);
            b[s] = dA * b[s] + dtxc * Bs_s[step][s];
            a[s] *= dA;
        }
    }
    int base = blk * (DI * DS) + d * DS;
    #pragma unroll
    for (int s = 0; s < DS; s++) { g_chA[base + s] = a[s]; g_chB[base + s] = b[s]; }
}

// ---------------- scan pass 2: sequential chunk combine ----------------
__global__ void scan2_k() {
    int tid = blockIdx.x * 256 + threadIdx.x;   // 0..4095 = d*16+s
    float h = 0.f;
    #pragma unroll 8
    for (int c = 0; c < NC; c++) {
        int idx = c * (DI * DS) + tid;
        g_h0[idx] = h;
        h = g_chA[idx] * h + g_chB[idx];
    }
}

// ---------------- scan pass 3: recompute with init state + fuse y ----------------
__global__ void scan3_k(const float* __restrict__ Alog, const float* __restrict__ Dp) {
    int blk = blockIdx.x, d = threadIdx.x;
    __shared__ float Bs_s[CH][DS], Cs_s[CH][DS];
    {
        int step = threadIdx.x >> 4, s = threadIdx.x & 15;
        int base = (blk * CH + step) * NPROJ + DTR;
        Bs_s[step][s] = g_dbl[base + s];
        Cs_s[step][s] = g_dbl[base + DS + s];
    }
    __syncthreads();
    float Arow[DS], h[DS];
    int hb = blk * (DI * DS) + d * DS;
    #pragma unroll
    for (int s = 0; s < DS; s++) {
        Arow[s] = -__expf(Alog[d * DS + s]);
        h[s] = g_h0[hb + s];
    }
    float Dd = Dp[d];
    #pragma unroll 4
    for (int step = 0; step < CH; step++) {
        int l = blk * CH + step;
        float dt = g_dt[l * DI + d], xc = g_xc[l * DI + d];
        float dtxc = dt * xc;
        float y = 0.f;
        #pragma unroll
        for (int s = 0; s < DS; s++) {
            float dA = __expf(dt * Arow[s]);
            h[s] = dA * h[s] + dtxc * Bs_s[step][s];
            y += h[s] * Cs_s[step][s];
        }
        y += Dd * xc;
        float z = g_xz[l * (2 * DI) + DI + d];
        float sz = z / (1.f + __expf(-z));
        g_y[l * DI + d] = y * sz;
    }
}

// ---------------- RMSNorm over DM=128 ----------------
__global__ void rms_k(const float* __restrict__ w) {
    int l = blockIdx.x, j = threadIdx.x;   // 128 threads
    float v = g_tmp[l * DM + j];
    float ss = v * v;
    #pragma unroll
    for (int o = 16; o > 0; o >>= 1) ss += __shfl_xor_sync(0xffffffffu, ss, o);
    __shared__ float sh[4];
    if ((j & 31) == 0) sh[j >> 5] = ss;
    __syncthreads();
    float tot = sh[0] + sh[1] + sh[2] + sh[3];
    float scale = rsqrtf(tot * (1.f / DM) + 1e-5f);
    g_seq[l * DM + j] = v * scale * w[j];
}

// ---------------- launch ----------------
extern "C" void kernel_launch(void* const* d_in, const int* in_sizes, int n_in,
                              void* d_out, int out_size) {
    const float* x      = (const float*)d_in[0];
    const float* W_in   = (const float*)d_in[1];
    const float* conv_w = (const float*)d_in[2];
    const float* conv_b = (const float*)d_in[3];
    const float* W_xp   = (const float*)d_in[4];
    const float* W_dt   = (const float*)d_in[5];
    const float* b_dt   = (const float*)d_in[6];
    const float* A_log  = (const float*)d_in[7];
    const float* D_skip = (const float*)d_in[8];
    const float* W_out  = (const float*)d_in[9];
    const float* rms_w  = (const float*)d_in[10];
    float* out = (float*)d_out;

    float *p_seq, *p_xz, *p_xc, *p_dbl, *p_y, *p_tmp;
    cudaGetSymbolAddress((void**)&p_seq, g_seq);
    cudaGetSymbolAddress((void**)&p_xz,  g_xz);
    cudaGetSymbolAddress((void**)&p_xc,  g_xc);
    cudaGetSymbolAddress((void**)&p_dbl, g_dbl);
    cudaGetSymbolAddress((void**)&p_y,   g_y);
    cudaGetSymbolAddress((void**)&p_tmp, g_tmp);

    dim3 tb(32, 8);
    transpose_in_k<<<dim3(L / 32, DM / 32), tb>>>(x);

    for (int l = 0; l < NDEPTH; l++) {
        const float* Wi  = W_in   + (size_t)l * DM * 2 * DI;
        const float* cw  = conv_w + (size_t)l * DI * 4;
        const float* cb  = conv_b + (size_t)l * DI;
        const float* Wx  = W_xp   + (size_t)l * DI * NPROJ;
        const float* Wd  = W_dt   + (size_t)l * DTR * DI;
        const float* bd  = b_dt   + (size_t)l * DI;
        const float* Al  = A_log  + (size_t)l * DI * DS;
        const float* Dp  = D_skip + (size_t)l * DI;
        const float* Wo  = W_out  + (size_t)l * DI * DM;
        const float* rw  = rms_w  + (size_t)l * DM;

        gemm_k<<<dim3(2 * DI / 64, L / 64), 256>>>(p_seq, Wi, p_xz, L, 2 * DI, DM);
        conv_silu_k<<<L, DI>>>(cw, cb);
        gemm_k<<<dim3(1, L / 64), 256>>>(p_xc, Wx, p_dbl, L, NPROJ, DI);
        dt_k<<<L, DI>>>(Wd, bd);
        scan1_k<<<NC, DI>>>(Al);
        scan2_k<<<DI * DS / 256, 256>>>();
        scan3_k<<<NC, DI>>>(Al, Dp);
        gemm_k<<<dim3(DM / 64, L / 64), 256>>>(p_y, Wo, p_tmp, L, DM, DI);
        rms_k<<<L, DM>>>(rw);
    }

    transpose_out_k<<<dim3(L / 32, DM / 32), tb>>>(out);
}

// round 3
// speedup vs baseline: 1.5262x; 1.5262x over previous
#include <cuda_runtime.h>
#include <math.h>

#define L      2304
#define DM     128
#define DI     256
#define DS     16
#define DTR    8
#define NPROJ  40   // DTR + 2*DS
#define NDEPTH 8
#define CHK    16
#define NC     (L/CHK)   // 144

// ---------------- scratch (device globals; no allocations) ----------------
__device__ float g_seq[L*DM];
__device__ float g_xz [L*2*DI];
__device__ float g_xc [L*DI];
__device__ float g_dbl[L*NPROJ];
__device__ float g_dt [L*DI];
__device__ float g_chA[NC*DI*DS];   // layout [chunk][s*DI + d]
__device__ float g_chB[NC*DI*DS];
__device__ float g_h0 [NC*DI*DS];

// ---------------- transpose in: x[c, l] -> seq[l, c] ----------------
__global__ void transpose_in_k(const float* __restrict__ x) {
    __shared__ float t[32][33];
    int l0 = blockIdx.x * 32, c0 = blockIdx.y * 32;
    int tx = threadIdx.x, ty = threadIdx.y;
    #pragma unroll
    for (int i = ty; i < 32; i += 8)
        t[i][tx] = x[(c0 + i) * L + l0 + tx];
    __syncthreads();
    #pragma unroll
    for (int i = ty; i < 32; i += 8)
        g_seq[(l0 + i) * DM + c0 + tx] = t[tx][i];
}

// ---------------- transpose out: seq[l, c] -> out[c, l] ----------------
__global__ void transpose_out_k(float* __restrict__ out) {
    __shared__ float t[32][33];
    int l0 = blockIdx.x * 32, c0 = blockIdx.y * 32;
    int tx = threadIdx.x, ty = threadIdx.y;
    #pragma unroll
    for (int i = ty; i < 32; i += 8)
        t[i][tx] = g_seq[(l0 + i) * DM + c0 + tx];
    __syncthreads();
    #pragma unroll
    for (int i = ty; i < 32; i += 8)
        out[(c0 + i) * L + l0 + tx] = t[tx][i];
}

// ---------------- in-proj GEMM: xz[L,512] = seq[L,128] @ Wi[128,512] ----------------
__global__ void __launch_bounds__(256) gemm_k(const float* __restrict__ A,
                                              const float* __restrict__ B,
                                              float* __restrict__ C,
                                              int M, int N, int K) {
    __shared__ float As[16][68];
    __shared__ float Bs[16][64];
    int tid = threadIdx.x;
    int tr = tid >> 4, tc = tid & 15;
    int row0 = blockIdx.y * 64, col0 = blockIdx.x * 64;
    float acc[4][4] = {};
    for (int k0 = 0; k0 < K; k0 += 16) {
        #pragma unroll
        for (int i = 0; i < 4; i++) {
            int li = i * 256 + tid;
            int k = li & 15, m = li >> 4;
            As[k][m] = A[(row0 + m) * K + k0 + k];
        }
        #pragma unroll
        for (int i = 0; i < 4; i++) {
            int li = i * 256 + tid;
            int n = li & 63, k = li >> 6;
            Bs[k][n] = B[(k0 + k) * N + col0 + n];
        }
        __syncthreads();
        #pragma unroll
        for (int k = 0; k < 16; k++) {
            float a[4], b[4];
            #pragma unroll
            for (int i = 0; i < 4; i++) a[i] = As[k][tr * 4 + i];
            #pragma unroll
            for (int j = 0; j < 4; j++) b[j] = Bs[k][tc * 4 + j];
            #pragma unroll
            for (int i = 0; i < 4; i++)
                #pragma unroll
                for (int j = 0; j < 4; j++)
                    acc[i][j] += a[i] * b[j];
        }
        __syncthreads();
    }
    #pragma unroll
    for (int i = 0; i < 4; i++) {
        int r = row0 + tr * 4 + i;
        #pragma unroll
        for (int j = 0; j < 4; j++)
            C[r * N + col0 + tc * 4 + j] = acc[i][j];
    }
}

// ======= fused: conv+SiLU -> xproj -> dt(softplus) -> scan pass 1 =======
// One block per 16-row chunk; 256 threads = one per d channel.
__global__ void __launch_bounds__(256) fused_mid_k(
    const float* __restrict__ cw, const float* __restrict__ cb,
    const float* __restrict__ Wx, const float* __restrict__ Wdt,
    const float* __restrict__ bdt, const float* __restrict__ Alog)
{
    __shared__ float xc_s[CHK * 257];     // [row][k], padded stride
    __shared__ float Wx_s[128 * 48];      // half-K tile of Wx, padded cols
    __shared__ float dbl_s[CHK * NPROJ];
    int t  = threadIdx.x;
    int l0 = blockIdx.x * CHK;

    float xcr[CHK], dtr[CHK];

    // ---- conv + SiLU (thread t owns channel d = t) ----
    {
        int d = t;
        float c0 = cw[d*4+0], c1 = cw[d*4+1], c2 = cw[d*4+2], c3 = cw[d*4+3];
        float bb = cb[d];
        #pragma unroll
        for (int r = 0; r < CHK; r++) {
            int l = l0 + r;
            float acc = bb + g_xz[l*512 + d] * c3;
            if (l >= 3) {
                acc += g_xz[(l-3)*512 + d] * c0
                     + g_xz[(l-2)*512 + d] * c1
                     + g_xz[(l-1)*512 + d] * c2;
            } else {
                if (l >= 3) acc += g_xz[(l-3)*512 + d] * c0;
                if (l >= 2) acc += g_xz[(l-2)*512 + d] * c1;
                if (l >= 1) acc += g_xz[(l-1)*512 + d] * c2;
            }
            acc = acc / (1.f + __expf(-acc));
            xcr[r] = acc;
            xc_s[r*257 + d] = acc;
            g_xc[l*DI + d] = acc;
        }
    }

    // ---- xproj: dbl[16,40] = xc[16,256] @ Wx[256,40], two K halves ----
    int row = t & 15, g = t >> 4;
    int c0i = g * 3;                 // 16 groups x 3 cols cover 40 (+8 dead)
    float a0 = 0.f, a1 = 0.f, a2 = 0.f;
    for (int p = 0; p < 2; p++) {
        __syncthreads();             // (p=0: xc_s ready; p=1: Wx_s reuse safe)
        for (int i = t; i < 128 * NPROJ; i += 256) {
            int k = i / NPROJ, c = i % NPROJ;
            Wx_s[k*48 + c] = Wx[(p*128 + k) * NPROJ + c];
        }
        __syncthreads();
        const float* xr = xc_s + row*257 + p*128;
        #pragma unroll 4
        for (int k = 0; k < 128; k++) {
            float xv = xr[k];
            a0 += xv * Wx_s[k*48 + c0i];
            a1 += xv * Wx_s[k*48 + c0i + 1];
            a2 += xv * Wx_s[k*48 + c0i + 2];
        }
    }
    if (c0i     < NPROJ) { dbl_s[row*NPROJ + c0i]     = a0; g_dbl[(l0+row)*NPROJ + c0i]     = a0; }
    if (c0i + 1 < NPROJ) { dbl_s[row*NPROJ + c0i + 1] = a1; g_dbl[(l0+row)*NPROJ + c0i + 1] = a1; }
    if (c0i + 2 < NPROJ) { dbl_s[row*NPROJ + c0i + 2] = a2; g_dbl[(l0+row)*NPROJ + c0i + 2] = a2; }
    __syncthreads();

    // ---- dt = softplus(dt_r @ Wdt + bdt), thread t owns channel d ----
    {
        int d = t;
        float w[DTR];
        #pragma unroll
        for (int k = 0; k < DTR; k++) w[k] = Wdt[k*DI + d];
        float bb = bdt[d];
        #pragma unroll
        for (int r = 0; r < CHK; r++) {
            float acc = bb;
            #pragma unroll
            for (int k = 0; k < DTR; k++) acc += dbl_s[r*NPROJ + k] * w[k];
            float sp = (acc > 20.f) ? acc : log1pf(__expf(acc));
            dtr[r] = sp;
            g_dt[(l0+r)*DI + d] = sp;
        }
    }

    // ---- scan pass 1: per-chunk (prod dA, local b) ----
    {
        int d = t;
        float Arow[DS], a[DS], b[DS];
        #pragma unroll
        for (int s = 0; s < DS; s++) {
            Arow[s] = -__expf(Alog[d*DS + s]);
            a[s] = 1.f; b[s] = 0.f;
        }
        #pragma unroll 4
        for (int r = 0; r < CHK; r++) {
            float dt = dtr[r], dtxc = dt * xcr[r];
            #pragma unroll
            for (int s = 0; s < DS; s++) {
                float dA = __expf(dt * Arow[s]);
                b[s] = dA * b[s] + dtxc * dbl_s[r*NPROJ + DTR + s];
                a[s] *= dA;
            }
        }
        int base = blockIdx.x * (DI*DS) + d;   // [chunk][s*DI + d]
        #pragma unroll
        for (int s = 0; s < DS; s++) {
            g_chA[base + s*DI] = a[s];
            g_chB[base + s*DI] = b[s];
        }
    }
}

// ---------------- scan pass 2: sequential chunk combine ----------------
__global__ void scan2_k() {
    int tid = blockIdx.x * 256 + threadIdx.x;   // 0..4095
    float h = 0.f;
    #pragma unroll 8
    for (int c = 0; c < NC; c++) {
        int idx = c * (DI*DS) + tid;
        g_h0[idx] = h;
        h = g_chA[idx] * h + g_chB[idx];
    }
}

// ======= fused: scan pass 3 + gate -> out-proj GEMM -> RMSNorm =======
__global__ void __launch_bounds__(256) fused_out_k(
    const float* __restrict__ Alog, const float* __restrict__ Dp,
    const float* __restrict__ Wo, const float* __restrict__ rw)
{
    __shared__ float y_s[CHK * DI];        // 16KB
    __shared__ float Wo_s[32 * DM];        // 16KB
    __shared__ float Bs_s[CHK][DS];
    __shared__ float Cs_s[CHK][DS];
    int t  = threadIdx.x;
    int l0 = blockIdx.x * CHK;

    {
        int r = t >> 4, s = t & 15;
        int base = (l0 + r) * NPROJ + DTR;
        Bs_s[r][s] = g_dbl[base + s];
        Cs_s[r][s] = g_dbl[base + DS + s];
    }
    __syncthreads();

    // ---- phase A: scan with init state, C-contract, D-skip, z-gate ----
    {
        int d = t;
        float Arow[DS], h[DS];
        int hb = blockIdx.x * (DI*DS) + d;
        #pragma unroll
        for (int s = 0; s < DS; s++) {
            Arow[s] = -__expf(Alog[d*DS + s]);
            h[s] = g_h0[hb + s*DI];
        }
        float Dd = Dp[d];
        #pragma unroll 4
        for (int r = 0; r < CHK; r++) {
            int l = l0 + r;
            float dt = g_dt[l*DI + d], xc = g_xc[l*DI + d];
            float dtxc = dt * xc;
            float y = Dd * xc;
            #pragma unroll
            for (int s = 0; s < DS; s++) {
                float dA = __expf(dt * Arow[s]);
                h[s] = dA * h[s] + dtxc * Bs_s[r][s];
                y += h[s] * Cs_s[r][s];
            }
            float z = g_xz[l*512 + DI + d];
            y *= z / (1.f + __expf(-z));
            y_s[r*DI + d] = y;
        }
    }

    // ---- phase B: out[16,128] = y[16,256] @ Wo[256,128], RMSNorm epilogue ----
    int w = t >> 5, lane = t & 31;
    int r0 = 2*w, r1 = 2*w + 1;
    int cb = lane * 4;
    float acc0[4] = {}, acc1[4] = {};
    for (int k0 = 0; k0 < DI; k0 += 32) {
        __syncthreads();
        #pragma unroll
        for (int i = 0; i < 4; i++) {
            int idx = t + 256*i;                 // 1024 float4s
            int kk = idx >> 5, c4 = idx & 31;
            ((float4*)Wo_s)[kk*32 + c4] = ((const float4*)(Wo + (k0+kk)*DM))[c4];
        }
        __syncthreads();
        #pragma unroll
        for (int kk = 0; kk < 32; kk += 4) {
            float4 y0 = *(const float4*)&y_s[r0*DI + k0 + kk];
            float4 y1 = *(const float4*)&y_s[r1*DI + k0 + kk];
            float ya0[4] = {y0.x, y0.y, y0.z, y0.w};
            float ya1[4] = {y1.x, y1.y, y1.z, y1.w};
            #pragma unroll
            for (int i = 0; i < 4; i++) {
                float4 wv = *(const float4*)&Wo_s[(kk+i)*DM + cb];
                acc0[0] += ya0[i]*wv.x; acc0[1] += ya0[i]*wv.y;
                acc0[2] += ya0[i]*wv.z; acc0[3] += ya0[i]*wv.w;
                acc1[0] += ya1[i]*wv.x; acc1[1] += ya1[i]*wv.y;
                acc1[2] += ya1[i]*wv.z; acc1[3] += ya1[i]*wv.w;
            }
        }
    }
    // RMSNorm (row = full 128 cols spread across the 32 lanes of this warp)
    float ss0 = acc0[0]*acc0[0] + acc0[1]*acc0[1] + acc0[2]*acc0[2] + acc0[3]*acc0[3];
    float ss1 = acc1[0]*acc1[0] + acc1[1]*acc1[1] + acc1[2]*acc1[2] + acc1[3]*acc1[3];
    #pragma unroll
    for (int o = 16; o > 0; o >>= 1) {
        ss0 += __shfl_xor_sync(0xffffffffu, ss0, o);
        ss1 += __shfl_xor_sync(0xffffffffu, ss1, o);
    }
    float sc0 = rsqrtf(ss0 * (1.f/DM) + 1e-5f);
    float sc1 = rsqrtf(ss1 * (1.f/DM) + 1e-5f);
    float4 rwv = *(const float4*)&rw[cb];
    float4 o0, o1;
    o0.x = acc0[0]*sc0*rwv.x; o0.y = acc0[1]*sc0*rwv.y;
    o0.z = acc0[2]*sc0*rwv.z; o0.w = acc0[3]*sc0*rwv.w;
    o1.x = acc1[0]*sc1*rwv.x; o1.y = acc1[1]*sc1*rwv.y;
    o1.z = acc1[2]*sc1*rwv.z; o1.w = acc1[3]*sc1*rwv.w;
    *(float4*)&g_seq[(l0 + r0)*DM + cb] = o0;
    *(float4*)&g_seq[(l0 + r1)*DM + cb] = o1;
}

// ---------------- launch ----------------
extern "C" void kernel_launch(void* const* d_in, const int* in_sizes, int n_in,
                              void* d_out, int out_size) {
    const float* x      = (const float*)d_in[0];
    const float* W_in   = (const float*)d_in[1];
    const float* conv_w = (const float*)d_in[2];
    const float* conv_b = (const float*)d_in[3];
    const float* W_xp   = (const float*)d_in[4];
    const float* W_dt   = (const float*)d_in[5];
    const float* b_dt   = (const float*)d_in[6];
    const float* A_log  = (const float*)d_in[7];
    const float* D_skip = (const float*)d_in[8];
    const float* W_out  = (const float*)d_in[9];
    const float* rms_w  = (const float*)d_in[10];
    float* out = (float*)d_out;

    float *p_seq, *p_xz;
    cudaGetSymbolAddress((void**)&p_seq, g_seq);
    cudaGetSymbolAddress((void**)&p_xz,  g_xz);

    dim3 tb(32, 8);
    transpose_in_k<<<dim3(L / 32, DM / 32), tb>>>(x);

    for (int l = 0; l < NDEPTH; l++) {
        const float* Wi  = W_in   + (size_t)l * DM * 2 * DI;
        const float* cw  = conv_w + (size_t)l * DI * 4;
        const float* cb  = conv_b + (size_t)l * DI;
        const float* Wx  = W_xp   + (size_t)l * DI * NPROJ;
        const float* Wd  = W_dt   + (size_t)l * DTR * DI;
        const float* bd  = b_dt   + (size_t)l * DI;
        const float* Al  = A_log  + (size_t)l * DI * DS;
        const float* Dpp = D_skip + (size_t)l * DI;
        const float* Wo  = W_out  + (size_t)l * DI * DM;
        const float* rw  = rms_w  + (size_t)l * DM;

        gemm_k<<<dim3(2 * DI / 64, L / 64), 256>>>(p_seq, Wi, p_xz, L, 2 * DI, DM);
        fused_mid_k<<<NC, 256>>>(cw, cb, Wx, Wd, bd, Al);
        scan2_k<<<DI * DS / 256, 256>>>();
        fused_out_k<<<NC, 256>>>(Al, Dpp, Wo, rw);
    }

    transpose_out_k<<<dim3(L / 32, DM / 32), tb>>>(out);
}

// round 4
// speedup vs baseline: 2.1186x; 1.3882x over previous
#include <cuda_runtime.h>
#include <math.h>

#define L      2304
#define DM     128
#define DI     256
#define DS     16
#define DTR    8
#define NPROJ  40   // DTR + 2*DS
#define NDEPTH 8
#define CHK    16
#define NC     (L/CHK)   // 144
#define NSEQ   (DI*DS)   // 4096
#define SEQT   32        // sequences per scan2 block

// ---------------- scratch (device globals; no allocations) ----------------
__device__ float g_seq[L*DM];
__device__ float g_xz [L*2*DI];
__device__ float g_xc [L*DI];
__device__ float g_dbl[L*NPROJ];
__device__ float g_dt [L*DI];
__device__ float g_chA[NC*NSEQ];   // layout [chunk][s*DI + d]
__device__ float g_chB[NC*NSEQ];
__device__ float g_h0 [NC*NSEQ];

// ---------------- transpose in: x[c, l] -> seq[l, c] ----------------
__global__ void transpose_in_k(const float* __restrict__ x) {
    __shared__ float t[32][33];
    int l0 = blockIdx.x * 32, c0 = blockIdx.y * 32;
    int tx = threadIdx.x, ty = threadIdx.y;
    #pragma unroll
    for (int i = ty; i < 32; i += 8)
        t[i][tx] = x[(c0 + i) * L + l0 + tx];
    __syncthreads();
    #pragma unroll
    for (int i = ty; i < 32; i += 8)
        g_seq[(l0 + i) * DM + c0 + tx] = t[tx][i];
}

// ---------------- transpose out: seq[l, c] -> out[c, l] ----------------
__global__ void transpose_out_k(float* __restrict__ out) {
    __shared__ float t[32][33];
    int l0 = blockIdx.x * 32, c0 = blockIdx.y * 32;
    int tx = threadIdx.x, ty = threadIdx.y;
    #pragma unroll
    for (int i = ty; i < 32; i += 8)
        t[i][tx] = g_seq[(l0 + i) * DM + c0 + tx];
    __syncthreads();
    #pragma unroll
    for (int i = ty; i < 32; i += 8)
        out[(c0 + i) * L + l0 + tx] = t[tx][i];
}

// ---------------- in-proj GEMM: xz[L,512] = seq[L,128] @ Wi[128,512] ----------------
__global__ void __launch_bounds__(256) gemm_k(const float* __restrict__ A,
                                              const float* __restrict__ B,
                                              float* __restrict__ C,
                                              int M, int N, int K) {
    __shared__ float As[16][68];
    __shared__ float Bs[16][64];
    int tid = threadIdx.x;
    int tr = tid >> 4, tc = tid & 15;
    int row0 = blockIdx.y * 64, col0 = blockIdx.x * 64;
    float acc[4][4] = {};
    for (int k0 = 0; k0 < K; k0 += 16) {
        #pragma unroll
        for (int i = 0; i < 4; i++) {
            int li = i * 256 + tid;
            int k = li & 15, m = li >> 4;
            As[k][m] = A[(row0 + m) * K + k0 + k];
        }
        #pragma unroll
        for (int i = 0; i < 4; i++) {
            int li = i * 256 + tid;
            int n = li & 63, k = li >> 6;
            Bs[k][n] = B[(k0 + k) * N + col0 + n];
        }
        __syncthreads();
        #pragma unroll
        for (int k = 0; k < 16; k++) {
            float a[4], b[4];
            #pragma unroll
            for (int i = 0; i < 4; i++) a[i] = As[k][tr * 4 + i];
            #pragma unroll
            for (int j = 0; j < 4; j++) b[j] = Bs[k][tc * 4 + j];
            #pragma unroll
            for (int i = 0; i < 4; i++)
                #pragma unroll
                for (int j = 0; j < 4; j++)
                    acc[i][j] += a[i] * b[j];
        }
        __syncthreads();
    }
    #pragma unroll
    for (int i = 0; i < 4; i++) {
        int r = row0 + tr * 4 + i;
        #pragma unroll
        for (int j = 0; j < 4; j++)
            C[r * N + col0 + tc * 4 + j] = acc[i][j];
    }
}

// ======= fused: conv+SiLU -> xproj -> dt(softplus) -> scan pass 1 =======
__global__ void __launch_bounds__(256) fused_mid_k(
    const float* __restrict__ cw, const float* __restrict__ cb,
    const float* __restrict__ Wx, const float* __restrict__ Wdt,
    const float* __restrict__ bdt, const float* __restrict__ Alog)
{
    __shared__ float xc_s[CHK * 257];
    __shared__ float Wx_s[128 * 48];
    __shared__ float dbl_s[CHK * NPROJ];
    int t  = threadIdx.x;
    int l0 = blockIdx.x * CHK;

    float xcr[CHK], dtr[CHK];

    // ---- conv + SiLU ----
    {
        int d = t;
        float c0 = cw[d*4+0], c1 = cw[d*4+1], c2 = cw[d*4+2], c3 = cw[d*4+3];
        float bb = cb[d];
        #pragma unroll
        for (int r = 0; r < CHK; r++) {
            int l = l0 + r;
            float acc = bb + g_xz[l*512 + d] * c3;
            if (l >= 3) {
                acc += g_xz[(l-3)*512 + d] * c0
                     + g_xz[(l-2)*512 + d] * c1
                     + g_xz[(l-1)*512 + d] * c2;
            } else {
                if (l >= 2) acc += g_xz[(l-2)*512 + d] * c1;
                if (l >= 1) acc += g_xz[(l-1)*512 + d] * c2;
            }
            acc = acc / (1.f + __expf(-acc));
            xcr[r] = acc;
            xc_s[r*257 + d] = acc;
            g_xc[l*DI + d] = acc;
        }
    }

    // ---- xproj: dbl[16,40] = xc[16,256] @ Wx[256,40] ----
    int row = t & 15, g = t >> 4;
    int c0i = g * 3;
    float a0 = 0.f, a1 = 0.f, a2 = 0.f;
    for (int p = 0; p < 2; p++) {
        __syncthreads();
        for (int i = t; i < 128 * NPROJ; i += 256) {
            int k = i / NPROJ, c = i % NPROJ;
            Wx_s[k*48 + c] = Wx[(p*128 + k) * NPROJ + c];
        }
        __syncthreads();
        const float* xr = xc_s + row*257 + p*128;
        #pragma unroll 4
        for (int k = 0; k < 128; k++) {
            float xv = xr[k];
            a0 += xv * Wx_s[k*48 + c0i];
            a1 += xv * Wx_s[k*48 + c0i + 1];
            a2 += xv * Wx_s[k*48 + c0i + 2];
        }
    }
    if (c0i     < NPROJ) { dbl_s[row*NPROJ + c0i]     = a0; g_dbl[(l0+row)*NPROJ + c0i]     = a0; }
    if (c0i + 1 < NPROJ) { dbl_s[row*NPROJ + c0i + 1] = a1; g_dbl[(l0+row)*NPROJ + c0i + 1] = a1; }
    if (c0i + 2 < NPROJ) { dbl_s[row*NPROJ + c0i + 2] = a2; g_dbl[(l0+row)*NPROJ + c0i + 2] = a2; }
    __syncthreads();

    // ---- dt = softplus ----
    {
        int d = t;
        float w[DTR];
        #pragma unroll
        for (int k = 0; k < DTR; k++) w[k] = Wdt[k*DI + d];
        float bb = bdt[d];
        #pragma unroll
        for (int r = 0; r < CHK; r++) {
            float acc = bb;
            #pragma unroll
            for (int k = 0; k < DTR; k++) acc += dbl_s[r*NPROJ + k] * w[k];
            float sp = (acc > 20.f) ? acc : log1pf(__expf(acc));
            dtr[r] = sp;
            g_dt[(l0+r)*DI + d] = sp;
        }
    }

    // ---- scan pass 1 ----
    {
        int d = t;
        float Arow[DS], a[DS], b[DS];
        #pragma unroll
        for (int s = 0; s < DS; s++) {
            Arow[s] = -__expf(Alog[d*DS + s]);
            a[s] = 1.f; b[s] = 0.f;
        }
        #pragma unroll 4
        for (int r = 0; r < CHK; r++) {
            float dt = dtr[r], dtxc = dt * xcr[r];
            #pragma unroll
            for (int s = 0; s < DS; s++) {
                float dA = __expf(dt * Arow[s]);
                b[s] = dA * b[s] + dtxc * dbl_s[r*NPROJ + DTR + s];
                a[s] *= dA;
            }
        }
        int base = blockIdx.x * NSEQ + d;
        #pragma unroll
        for (int s = 0; s < DS; s++) {
            g_chA[base + s*DI] = a[s];
            g_chB[base + s*DI] = b[s];
        }
    }
}

// ======= scan pass 2: warp-parallel Kogge-Stone chunk combine =======
// 128 blocks x 256 thr; block owns 32 consecutive sequences. Smem-staged,
// all global traffic coalesced; affine compose via shuffles.
__global__ void __launch_bounds__(256) scan2_k() {
    __shared__ float A_s[NC][SEQT + 1];
    __shared__ float B_s[NC][SEQT + 1];
    int t = threadIdx.x;
    int w = t >> 5, lane = t & 31;
    int seq0 = blockIdx.x * SEQT;

    // coalesced load: warp w loads rows c = w, w+8, ...
    for (int c = w; c < NC; c += 8) {
        A_s[c][lane] = g_chA[c * NSEQ + seq0 + lane];
        B_s[c][lane] = g_chB[c * NSEQ + seq0 + lane];
    }
    __syncthreads();

    // each warp scans 4 sequences (its own smem columns)
    #pragma unroll
    for (int q = 0; q < 4; q++) {
        int col = w * 4 + q;
        float H = 0.f;                       // running state
        #pragma unroll
        for (int k = 0; k < 5; k++) {
            int c = k * 32 + lane;
            float ia, ib;
            if (c < NC) { ia = A_s[c][col]; ib = B_s[c][col]; }
            else        { ia = 1.f;         ib = 0.f; }
            // Kogge-Stone inclusive scan of affine composition
            #pragma unroll
            for (int off = 1; off < 32; off <<= 1) {
                float pa = __shfl_up_sync(0xffffffffu, ia, off);
                float pb = __shfl_up_sync(0xffffffffu, ib, off);
                if (lane >= off) { ib = ia * pb + ib; ia = ia * pa; }
            }
            // exclusive prefix for this lane
            float ea = __shfl_up_sync(0xffffffffu, ia, 1);
            float eb = __shfl_up_sync(0xffffffffu, ib, 1);
            if (lane == 0) { ea = 1.f; eb = 0.f; }
            if (c < NC) A_s[c][col] = ea * H + eb;   // h0[c]
            // carry = inclusive at lane 31 applied to H
            float ta = __shfl_sync(0xffffffffu, ia, 31);
            float tb = __shfl_sync(0xffffffffu, ib, 31);
            H = ta * H + tb;
        }
    }
    __syncthreads();

    // coalesced writeback of h0
    for (int c = w; c < NC; c += 8)
        g_h0[c * NSEQ + seq0 + lane] = A_s[c][lane];
}

// ======= fused: scan pass 3 + gate -> out-proj GEMM -> RMSNorm =======
__global__ void __launch_bounds__(256) fused_out_k(
    const float* __restrict__ Alog, const float* __restrict__ Dp,
    const float* __restrict__ Wo, const float* __restrict__ rw)
{
    __shared__ float y_s[CHK * DI];
    __shared__ float Wo_s[32 * DM];
    __shared__ float Bs_s[CHK][DS];
    __shared__ float Cs_s[CHK][DS];
    int t  = threadIdx.x;
    int l0 = blockIdx.x * CHK;

    {
        int r = t >> 4, s = t & 15;
        int base = (l0 + r) * NPROJ + DTR;
        Bs_s[r][s] = g_dbl[base + s];
        Cs_s[r][s] = g_dbl[base + DS + s];
    }
    __syncthreads();

    // ---- phase A: scan with init state, C-contract, D-skip, z-gate ----
    {
        int d = t;
        float Arow[DS], h[DS];
        int hb = blockIdx.x * NSEQ + d;
        #pragma unroll
        for (int s = 0; s < DS; s++) {
            Arow[s] = -__expf(Alog[d*DS + s]);
            h[s] = g_h0[hb + s*DI];
        }
        float Dd = Dp[d];
        #pragma unroll 4
        for (int r = 0; r < CHK; r++) {
            int l = l0 + r;
            float dt = g_dt[l*DI + d], xc = g_xc[l*DI + d];
            float dtxc = dt * xc;
            float y = Dd * xc;
            #pragma unroll
            for (int s = 0; s < DS; s++) {
                float dA = __expf(dt * Arow[s]);
                h[s] = dA * h[s] + dtxc * Bs_s[r][s];
                y += h[s] * Cs_s[r][s];
            }
            float z = g_xz[l*512 + DI + d];
            y *= z / (1.f + __expf(-z));
            y_s[r*DI + d] = y;
        }
    }

    // ---- phase B: out[16,128] = y[16,256] @ Wo[256,128] + RMSNorm ----
    int w = t >> 5, lane = t & 31;
    int r0 = 2*w, r1 = 2*w + 1;
    int cb = lane * 4;
    float acc0[4] = {}, acc1[4] = {};
    for (int k0 = 0; k0 < DI; k0 += 32) {
        __syncthreads();
        #pragma unroll
        for (int i = 0; i < 4; i++) {
            int idx = t + 256*i;
            int kk = idx >> 5, c4 = idx & 31;
            ((float4*)Wo_s)[kk*32 + c4] = ((const float4*)(Wo + (k0+kk)*DM))[c4];
        }
        __syncthreads();
        #pragma unroll
        for (int kk = 0; kk < 32; kk += 4) {
            float4 y0 = *(const float4*)&y_s[r0*DI + k0 + kk];
            float4 y1 = *(const float4*)&y_s[r1*DI + k0 + kk];
            float ya0[4] = {y0.x, y0.y, y0.z, y0.w};
            float ya1[4] = {y1.x, y1.y, y1.z, y1.w};
            #pragma unroll
            for (int i = 0; i < 4; i++) {
                float4 wv = *(const float4*)&Wo_s[(kk+i)*DM + cb];
                acc0[0] += ya0[i]*wv.x; acc0[1] += ya0[i]*wv.y;
                acc0[2] += ya0[i]*wv.z; acc0[3] += ya0[i]*wv.w;
                acc1[0] += ya1[i]*wv.x; acc1[1] += ya1[i]*wv.y;
                acc1[2] += ya1[i]*wv.z; acc1[3] += ya1[i]*wv.w;
            }
        }
    }
    float ss0 = acc0[0]*acc0[0] + acc0[1]*acc0[1] + acc0[2]*acc0[2] + acc0[3]*acc0[3];
    float ss1 = acc1[0]*acc1[0] + acc1[1]*acc1[1] + acc1[2]*acc1[2] + acc1[3]*acc1[3];
    #pragma unroll
    for (int o = 16; o > 0; o >>= 1) {
        ss0 += __shfl_xor_sync(0xffffffffu, ss0, o);
        ss1 += __shfl_xor_sync(0xffffffffu, ss1, o);
    }
    float sc0 = rsqrtf(ss0 * (1.f/DM) + 1e-5f);
    float sc1 = rsqrtf(ss1 * (1.f/DM) + 1e-5f);
    float4 rwv = *(const float4*)&rw[cb];
    float4 o0, o1;
    o0.x = acc0[0]*sc0*rwv.x; o0.y = acc0[1]*sc0*rwv.y;
    o0.z = acc0[2]*sc0*rwv.z; o0.w = acc0[3]*sc0*rwv.w;
    o1.x = acc1[0]*sc1*rwv.x; o1.y = acc1[1]*sc1*rwv.y;
    o1.z = acc1[2]*sc1*rwv.z; o1.w = acc1[3]*sc1*rwv.w;
    *(float4*)&g_seq[(l0 + r0)*DM + cb] = o0;
    *(float4*)&g_seq[(l0 + r1)*DM + cb] = o1;
}

// ---------------- launch ----------------
extern "C" void kernel_launch(void* const* d_in, const int* in_sizes, int n_in,
                              void* d_out, int out_size) {
    const float* x      = (const float*)d_in[0];
    const float* W_in   = (const float*)d_in[1];
    const float* conv_w = (const float*)d_in[2];
    const float* conv_b = (const float*)d_in[3];
    const float* W_xp   = (const float*)d_in[4];
    const float* W_dt   = (const float*)d_in[5];
    const float* b_dt   = (const float*)d_in[6];
    const float* A_log  = (const float*)d_in[7];
    const float* D_skip = (const float*)d_in[8];
    const float* W_out  = (const float*)d_in[9];
    const float* rms_w  = (const float*)d_in[10];
    float* out = (float*)d_out;

    float *p_seq, *p_xz;
    cudaGetSymbolAddress((void**)&p_seq, g_seq);
    cudaGetSymbolAddress((void**)&p_xz,  g_xz);

    dim3 tb(32, 8);
    transpose_in_k<<<dim3(L / 32, DM / 32), tb>>>(x);

    for (int l = 0; l < NDEPTH; l++) {
        const float* Wi  = W_in   + (size_t)l * DM * 2 * DI;
        const float* cw  = conv_w + (size_t)l * DI * 4;
        const float* cb  = conv_b + (size_t)l * DI;
        const float* Wx  = W_xp   + (size_t)l * DI * NPROJ;
        const float* Wd  = W_dt   + (size_t)l * DTR * DI;
        const float* bd  = b_dt   + (size_t)l * DI;
        const float* Al  = A_log  + (size_t)l * DI * DS;
        const float* Dpp = D_skip + (size_t)l * DI;
        const float* Wo  = W_out  + (size_t)l * DI * DM;
        const float* rw  = rms_w  + (size_t)l * DM;

        gemm_k<<<dim3(2 * DI / 64, L / 64), 256>>>(p_seq, Wi, p_xz, L, 2 * DI, DM);
        fused_mid_k<<<NC, 256>>>(cw, cb, Wx, Wd, bd, Al);
        scan2_k<<<NSEQ / SEQT, 256>>>();
        fused_out_k<<<NC, 256>>>(Al, Dpp, Wo, rw);
    }

    transpose_out_k<<<dim3(L / 32, DM / 32), tb>>>(out);
}